// round 1
// baseline (speedup 1.0000x reference)
#include <cuda_runtime.h>
#include <math.h>

#define BB 64
#define SS 2048
#define DD 1024
#define NEGV (-1000000000.0f)

// Scratch (no allocations allowed)
__device__ float g_dec_proj[BB * DD];
__device__ float g_scores[BB * SS];

// ---------------------------------------------------------------------------
// K1: dec_proj[b][d] = sum_k dh[b][k] * Wdec[d][k]
// 64x64 tile per block (all 64 b rows, 64 d cols), grid = D/64 = 16 blocks.
// ---------------------------------------------------------------------------
__global__ __launch_bounds__(256) void dec_proj_kernel(
    const float* __restrict__ dh, const float* __restrict__ Wdec) {
    __shared__ float As[16][64];
    __shared__ float Bs[16][64];
    const int tid = threadIdx.x;
    const int d0 = blockIdx.x * 64;
    const int tx = tid % 16;      // d micro
    const int ty = tid / 16;      // b micro
    const int lrow = tid / 4;     // 0..63
    const int lk = (tid % 4) * 4; // 0,4,8,12

    float acc[4][4];
#pragma unroll
    for (int i = 0; i < 4; i++)
#pragma unroll
        for (int j = 0; j < 4; j++) acc[i][j] = 0.f;

    for (int k0 = 0; k0 < DD; k0 += 16) {
        float4 av = *(const float4*)(dh + (size_t)lrow * DD + k0 + lk);
        float4 bv = *(const float4*)(Wdec + (size_t)(d0 + lrow) * DD + k0 + lk);
        __syncthreads();
        As[lk + 0][lrow] = av.x; As[lk + 1][lrow] = av.y;
        As[lk + 2][lrow] = av.z; As[lk + 3][lrow] = av.w;
        Bs[lk + 0][lrow] = bv.x; Bs[lk + 1][lrow] = bv.y;
        Bs[lk + 2][lrow] = bv.z; Bs[lk + 3][lrow] = bv.w;
        __syncthreads();
#pragma unroll
        for (int k = 0; k < 16; k++) {
            float a[4], bb[4];
#pragma unroll
            for (int i = 0; i < 4; i++) a[i] = As[k][ty * 4 + i];
#pragma unroll
            for (int j = 0; j < 4; j++) bb[j] = Bs[k][tx * 4 + j];
#pragma unroll
            for (int i = 0; i < 4; i++)
#pragma unroll
                for (int j = 0; j < 4; j++) acc[i][j] += a[i] * bb[j];
        }
    }
#pragma unroll
    for (int i = 0; i < 4; i++)
#pragma unroll
        for (int j = 0; j < 4; j++)
            g_dec_proj[(size_t)(ty * 4 + i) * DD + d0 + tx * 4 + j] = acc[i][j];
}

// ---------------------------------------------------------------------------
// K2: fused  enc_proj -> tanh -> v-dot -> scores
// Block: 128 (s) x 64 (d) tile, BK=16, 256 threads, 8x4 micro-tile.
// Loops over all 16 d-tiles so the per-row score reduces inside one block
// (deterministic: shuffle reduce across tx, single-lane smem add per row).
// Grid: (S/128, B) = (16, 64).
// ---------------------------------------------------------------------------
__global__ __launch_bounds__(256) void scores_kernel(
    const float* __restrict__ E, const float* __restrict__ Wenc,
    const float* __restrict__ v) {
    __shared__ float As[16][128];
    __shared__ float Bs[16][64];
    __shared__ float sc[128];

    const int tid = threadIdx.x;
    const int b = blockIdx.y;
    const int s0 = blockIdx.x * 128;
    const int tx = tid % 16;  // d micro (4 cols)
    const int ty = tid / 16;  // s micro (8 rows)
    const int lrow = tid / 4;
    const int lk = (tid % 4) * 4;

    if (tid < 128) sc[tid] = 0.f;

    const float* Eb = E + (size_t)b * SS * DD;

    for (int n0 = 0; n0 < DD; n0 += 64) {
        float acc[8][4];
#pragma unroll
        for (int i = 0; i < 8; i++)
#pragma unroll
            for (int j = 0; j < 4; j++) acc[i][j] = 0.f;

        for (int k0 = 0; k0 < DD; k0 += 16) {
            float4 a0 = *(const float4*)(Eb + (size_t)(s0 + lrow) * DD + k0 + lk);
            float4 a1 = *(const float4*)(Eb + (size_t)(s0 + 64 + lrow) * DD + k0 + lk);
            float4 bv = *(const float4*)(Wenc + (size_t)(n0 + lrow) * DD + k0 + lk);
            __syncthreads();
            As[lk + 0][lrow] = a0.x; As[lk + 1][lrow] = a0.y;
            As[lk + 2][lrow] = a0.z; As[lk + 3][lrow] = a0.w;
            As[lk + 0][64 + lrow] = a1.x; As[lk + 1][64 + lrow] = a1.y;
            As[lk + 2][64 + lrow] = a1.z; As[lk + 3][64 + lrow] = a1.w;
            Bs[lk + 0][lrow] = bv.x; Bs[lk + 1][lrow] = bv.y;
            Bs[lk + 2][lrow] = bv.z; Bs[lk + 3][lrow] = bv.w;
            __syncthreads();
#pragma unroll
            for (int k = 0; k < 16; k++) {
                float a[8], bb[4];
#pragma unroll
                for (int i = 0; i < 8; i++) a[i] = As[k][ty * 8 + i];
#pragma unroll
                for (int j = 0; j < 4; j++) bb[j] = Bs[k][tx * 4 + j];
#pragma unroll
                for (int i = 0; i < 8; i++)
#pragma unroll
                    for (int j = 0; j < 4; j++) acc[i][j] += a[i] * bb[j];
            }
        }

        // epilogue for this d-tile: tanh + v-dot
        float vv[4], dp[4];
#pragma unroll
        for (int j = 0; j < 4; j++) {
            int d = n0 + tx * 4 + j;
            vv[j] = v[d];
            dp[j] = g_dec_proj[(size_t)b * DD + d];
        }
        float sp[8];
#pragma unroll
        for (int i = 0; i < 8; i++) {
            float s = 0.f;
#pragma unroll
            for (int j = 0; j < 4; j++) {
                float e = tanhf(acc[i][j] + dp[j]);
                s += vv[j] * e;
            }
            sp[i] = s;
        }
        // reduce across tx (lanes xor 1,2,4,8 stay within each 16-lane half)
#pragma unroll
        for (int off = 8; off >= 1; off >>= 1)
#pragma unroll
            for (int i = 0; i < 8; i++)
                sp[i] += __shfl_xor_sync(0xffffffffu, sp[i], off);
        if (tx == 0) {
#pragma unroll
            for (int i = 0; i < 8; i++) sc[ty * 8 + i] += sp[i];
        }
    }
    __syncthreads();
    if (tid < 128) g_scores[(size_t)b * SS + s0 + tid] = sc[tid];
}

// ---------------------------------------------------------------------------
// K3: masked softmax over S per batch row. Writes attn into d_out tail.
// ---------------------------------------------------------------------------
__global__ __launch_bounds__(256) void softmax_kernel(
    const int* __restrict__ mask, float* __restrict__ out) {
    __shared__ float red[256];
    const int b = blockIdx.x;
    const int tid = threadIdx.x;
    float vals[8];
    float mx = -INFINITY;
#pragma unroll
    for (int i = 0; i < 8; i++) {
        int s = tid + i * 256;
        float scv = g_scores[(size_t)b * SS + s];
        if (mask[(size_t)b * SS + s] == 0) scv = NEGV;
        vals[i] = scv;
        mx = fmaxf(mx, scv);
    }
    red[tid] = mx;
    __syncthreads();
    for (int off = 128; off >= 1; off >>= 1) {
        if (tid < off) red[tid] = fmaxf(red[tid], red[tid + off]);
        __syncthreads();
    }
    mx = red[0];
    __syncthreads();
    float sum = 0.f;
#pragma unroll
    for (int i = 0; i < 8; i++) {
        vals[i] = expf(vals[i] - mx);
        sum += vals[i];
    }
    red[tid] = sum;
    __syncthreads();
    for (int off = 128; off >= 1; off >>= 1) {
        if (tid < off) red[tid] += red[tid + off];
        __syncthreads();
    }
    float inv = 1.f / red[0];
#pragma unroll
    for (int i = 0; i < 8; i++)
        out[(size_t)BB * DD + (size_t)b * SS + tid + i * 256] = vals[i] * inv;
}

// ---------------------------------------------------------------------------
// K4: context[b][e] = sum_s attn[b][s] * E[b][s][e]
// Grid (D/256, B); attn staged in smem once per block.
// ---------------------------------------------------------------------------
__global__ __launch_bounds__(256) void context_kernel(
    const float* __restrict__ E, float* __restrict__ out) {
    __shared__ float a_s[SS];
    const int b = blockIdx.y;
    const int e = blockIdx.x * 256 + threadIdx.x;
    const float* attn = out + (size_t)BB * DD + (size_t)b * SS;
    for (int i = threadIdx.x; i < SS; i += 256) a_s[i] = attn[i];
    __syncthreads();
    const float* Ebe = E + (size_t)b * SS * DD + e;
    float c = 0.f;
#pragma unroll 8
    for (int s = 0; s < SS; s++) c += a_s[s] * Ebe[(size_t)s * DD];
    out[(size_t)b * DD + e] = c;
}

// ---------------------------------------------------------------------------
extern "C" void kernel_launch(void* const* d_in, const int* in_sizes, int n_in,
                              void* d_out, int out_size) {
    const float* dh   = (const float*)d_in[0];  // [64,1024]
    const float* E    = (const float*)d_in[1];  // [64,2048,1024]
    const int*   mask = (const int*)d_in[2];    // [64,2048]
    const float* Wenc = (const float*)d_in[3];  // [1024,1024]
    const float* Wdec = (const float*)d_in[4];  // [1024,1024]
    const float* v    = (const float*)d_in[5];  // [1024]
    float* out = (float*)d_out;                 // context [64,1024] ++ attn [64,2048]

    dec_proj_kernel<<<DD / 64, 256>>>(dh, Wdec);
    dim3 g2(SS / 128, BB);
    scores_kernel<<<g2, 256>>>(E, Wenc, v);
    softmax_kernel<<<BB, 256>>>(mask, out);
    dim3 g4(DD / 256, BB);
    context_kernel<<<g4, 256>>>(E, out);
}

// round 4
// speedup vs baseline: 2.3352x; 2.3352x over previous
#include <cuda_runtime.h>
#include <cuda_bf16.h>
#include <math.h>

#define BB 64
#define SS 2048
#define DD 1024
#define NEGV (-1000000000.0f)

// Scratch (no allocations allowed)
__device__ float g_dec_proj[BB * DD];
__device__ float g_scores[BB * SS];

// ---------------- helpers ----------------
__device__ __forceinline__ unsigned smem_u32(const void* p) {
    unsigned a;
    asm("{ .reg .u64 t; cvta.to.shared.u64 t, %1; cvt.u32.u64 %0, t; }"
        : "=r"(a) : "l"(p));
    return a;
}

__device__ __forceinline__ void ldsm4(unsigned r[4], unsigned addr) {
    asm volatile("ldmatrix.sync.aligned.m8n8.x4.shared.b16 {%0,%1,%2,%3}, [%4];"
                 : "=r"(r[0]), "=r"(r[1]), "=r"(r[2]), "=r"(r[3]) : "r"(addr));
}

__device__ __forceinline__ void mma16816(float c[4], const unsigned a[4],
                                         unsigned b0, unsigned b1) {
    asm volatile(
        "mma.sync.aligned.m16n8k16.row.col.f32.bf16.bf16.f32 "
        "{%0,%1,%2,%3},{%4,%5,%6,%7},{%8,%9},{%0,%1,%2,%3};"
        : "+f"(c[0]), "+f"(c[1]), "+f"(c[2]), "+f"(c[3])
        : "r"(a[0]), "r"(a[1]), "r"(a[2]), "r"(a[3]), "r"(b0), "r"(b1));
}

__device__ __forceinline__ float tanha(float x) {
    float y;
    asm("tanh.approx.f32 %0, %1;" : "=f"(y) : "f"(x));
    return y;
}

// hi/lo bf16 split of 4 floats, stored at H[idx..idx+3], L[idx..idx+3]
__device__ __forceinline__ void cvt_store(__nv_bfloat16* H, __nv_bfloat16* L,
                                          int idx, float4 vv) {
    __nv_bfloat16 h0 = __float2bfloat16_rn(vv.x);
    __nv_bfloat16 h1 = __float2bfloat16_rn(vv.y);
    __nv_bfloat16 h2 = __float2bfloat16_rn(vv.z);
    __nv_bfloat16 h3 = __float2bfloat16_rn(vv.w);
    float l0 = vv.x - __bfloat162float(h0);
    float l1 = vv.y - __bfloat162float(h1);
    float l2 = vv.z - __bfloat162float(h2);
    float l3 = vv.w - __bfloat162float(h3);
    __nv_bfloat162* ph = (__nv_bfloat162*)(H + idx);
    ph[0] = __halves2bfloat162(h0, h1);
    ph[1] = __halves2bfloat162(h2, h3);
    __nv_bfloat162* pl = (__nv_bfloat162*)(L + idx);
    pl[0] = __halves2bfloat162(__float2bfloat16_rn(l0), __float2bfloat16_rn(l1));
    pl[1] = __halves2bfloat162(__float2bfloat16_rn(l2), __float2bfloat16_rn(l3));
}

// smem layout (bytes), row stride = 40 bf16 (pad 8) => conflict-free ldmatrix
#define ES_HI 0
#define ES_LO 10240
#define WS_HI 20480
#define WS_LO 40960
#define SCP_OFF 61440
#define SMEM_TOTAL (61440 + 1024)

// ---------------------------------------------------------------------------
// K1: dec_proj[b][d] = sum_k dh[b][k] * Wdec[d][k]
// ---------------------------------------------------------------------------
__global__ __launch_bounds__(256) void dec_proj_kernel(
    const float* __restrict__ dh, const float* __restrict__ Wdec) {
    __shared__ float As[16][64];
    __shared__ float Bs[16][64];
    const int tid = threadIdx.x;
    const int d0 = blockIdx.x * 64;
    const int tx = tid % 16;
    const int ty = tid / 16;
    const int lrow = tid / 4;
    const int lk = (tid % 4) * 4;

    float acc[4][4];
#pragma unroll
    for (int i = 0; i < 4; i++)
#pragma unroll
        for (int j = 0; j < 4; j++) acc[i][j] = 0.f;

    for (int k0 = 0; k0 < DD; k0 += 16) {
        float4 av = *(const float4*)(dh + (size_t)lrow * DD + k0 + lk);
        float4 bv = *(const float4*)(Wdec + (size_t)(d0 + lrow) * DD + k0 + lk);
        __syncthreads();
        As[lk + 0][lrow] = av.x; As[lk + 1][lrow] = av.y;
        As[lk + 2][lrow] = av.z; As[lk + 3][lrow] = av.w;
        Bs[lk + 0][lrow] = bv.x; Bs[lk + 1][lrow] = bv.y;
        Bs[lk + 2][lrow] = bv.z; Bs[lk + 3][lrow] = bv.w;
        __syncthreads();
#pragma unroll
        for (int k = 0; k < 16; k++) {
            float a[4], bb[4];
#pragma unroll
            for (int i = 0; i < 4; i++) a[i] = As[k][ty * 4 + i];
#pragma unroll
            for (int j = 0; j < 4; j++) bb[j] = Bs[k][tx * 4 + j];
#pragma unroll
            for (int i = 0; i < 4; i++)
#pragma unroll
                for (int j = 0; j < 4; j++) acc[i][j] += a[i] * bb[j];
        }
    }
#pragma unroll
    for (int i = 0; i < 4; i++)
#pragma unroll
        for (int j = 0; j < 4; j++)
            g_dec_proj[(size_t)(ty * 4 + i) * DD + d0 + tx * 4 + j] = acc[i][j];
}

// ---------------------------------------------------------------------------
// K2 v2: tensor-core scores. CTA tile: 128 s x 256 d, k-chunk 32, bf16x3.
// Warp layout: 8 warps = 4 (m: 32 rows) x 2 (n: 128 cols).
// Grid: (S/128, B) = (16, 64).
// ---------------------------------------------------------------------------
__global__ __launch_bounds__(256) void scores_v2(
    const float* __restrict__ E, const float* __restrict__ W,
    const float* __restrict__ v) {
    extern __shared__ char sm[];
    __nv_bfloat16* EH = (__nv_bfloat16*)(sm + ES_HI);
    __nv_bfloat16* EL = (__nv_bfloat16*)(sm + ES_LO);
    __nv_bfloat16* WH = (__nv_bfloat16*)(sm + WS_HI);
    __nv_bfloat16* WL = (__nv_bfloat16*)(sm + WS_LO);
    float* scp = (float*)(sm + SCP_OFF);  // [2][128]

    const int tid = threadIdx.x;
    const int lane = tid & 31, wid = tid >> 5;
    const int wm = wid & 3, wn = wid >> 2;
    const int g = lane >> 2, t4 = lane & 3;
    const int b = blockIdx.y, s0 = blockIdx.x * 128;

    if (tid < 128) { scp[tid] = 0.f; scp[128 + tid] = 0.f; }

    const float* Eb = E + (size_t)b * SS * DD + (size_t)s0 * DD;

    const int lrow = tid >> 3;       // 0..31
    const int lkq = (tid & 7) * 4;   // 0..28
    const int lm = lane >> 3, lr = lane & 7;

    const unsigned eh_b = smem_u32(EH), el_b = smem_u32(EL);
    const unsigned wh_b = smem_u32(WH), wl_b = smem_u32(WL);

    for (int n0 = 0; n0 < DD; n0 += 256) {
        float acc[2][16][4];
#pragma unroll
        for (int mt = 0; mt < 2; mt++)
#pragma unroll
            for (int j = 0; j < 16; j++)
#pragma unroll
                for (int c = 0; c < 4; c++) acc[mt][j][c] = 0.f;

        for (int k0 = 0; k0 < DD; k0 += 32) {
            float4 ev[4], wv[8];
#pragma unroll
            for (int i = 0; i < 4; i++)
                ev[i] = *(const float4*)(Eb + (size_t)(lrow + 32 * i) * DD + k0 + lkq);
#pragma unroll
            for (int i = 0; i < 8; i++)
                wv[i] = *(const float4*)(W + (size_t)(n0 + lrow + 32 * i) * DD + k0 + lkq);
            __syncthreads();  // previous mma done reading smem
#pragma unroll
            for (int i = 0; i < 4; i++)
                cvt_store(EH, EL, (lrow + 32 * i) * 40 + lkq, ev[i]);
#pragma unroll
            for (int i = 0; i < 8; i++)
                cvt_store(WH, WL, (lrow + 32 * i) * 40 + lkq, wv[i]);
            __syncthreads();  // smem ready

#pragma unroll
            for (int kk = 0; kk < 2; kk++) {
                unsigned ah[2][4], al[2][4];
#pragma unroll
                for (int mt = 0; mt < 2; mt++) {
                    unsigned off =
                        ((32 * wm + 16 * mt + (lm & 1) * 8 + lr) * 40 +
                         kk * 16 + (lm >> 1) * 8) * 2;
                    ldsm4(ah[mt], eh_b + off);
                    ldsm4(al[mt], el_b + off);
                }
#pragma unroll
                for (int j2 = 0; j2 < 8; j2++) {
                    unsigned boff =
                        ((128 * wn + 8 * (2 * j2 + (lm >> 1)) + lr) * 40 +
                         kk * 16 + (lm & 1) * 8) * 2;
                    unsigned bh[4], bl[4];
                    ldsm4(bh, wh_b + boff);
                    ldsm4(bl, wl_b + boff);
#pragma unroll
                    for (int jj = 0; jj < 2; jj++) {
                        const int j = 2 * j2 + jj;
#pragma unroll
                        for (int mt = 0; mt < 2; mt++) {
                            mma16816(acc[mt][j], ah[mt], bh[2 * jj], bh[2 * jj + 1]);
                            mma16816(acc[mt][j], ah[mt], bl[2 * jj], bl[2 * jj + 1]);
                            mma16816(acc[mt][j], al[mt], bh[2 * jj], bh[2 * jj + 1]);
                        }
                    }
                }
            }
        }

        // epilogue: tanh + v-dot for this 256-d chunk
        float p[2][2] = {{0.f, 0.f}, {0.f, 0.f}};
        const float* dpb = g_dec_proj + (size_t)b * DD + n0 + 128 * wn;
        const float* vb = v + n0 + 128 * wn;
#pragma unroll
        for (int mt = 0; mt < 2; mt++) {
#pragma unroll
            for (int j = 0; j < 16; j++) {
                const int c0 = 8 * j + 2 * t4;
                const float dp0 = dpb[c0], dp1 = dpb[c0 + 1];
                const float v0 = vb[c0], v1 = vb[c0 + 1];
                p[mt][0] += v0 * tanha(acc[mt][j][0] + dp0) +
                            v1 * tanha(acc[mt][j][1] + dp1);
                p[mt][1] += v0 * tanha(acc[mt][j][2] + dp0) +
                            v1 * tanha(acc[mt][j][3] + dp1);
            }
        }
#pragma unroll
        for (int off = 1; off <= 2; off <<= 1)
#pragma unroll
            for (int mt = 0; mt < 2; mt++)
#pragma unroll
                for (int rp = 0; rp < 2; rp++)
                    p[mt][rp] += __shfl_xor_sync(0xffffffffu, p[mt][rp], off);
        if (t4 == 0) {
#pragma unroll
            for (int mt = 0; mt < 2; mt++)
#pragma unroll
                for (int rp = 0; rp < 2; rp++)
                    scp[wn * 128 + 32 * wm + 16 * mt + g + 8 * rp] += p[mt][rp];
        }
    }
    __syncthreads();
    if (tid < 128)
        g_scores[(size_t)b * SS + s0 + tid] = scp[tid] + scp[128 + tid];
}

// ---------------------------------------------------------------------------
// K3: masked softmax per batch row
// ---------------------------------------------------------------------------
__global__ __launch_bounds__(256) void softmax_kernel(
    const int* __restrict__ mask, float* __restrict__ out) {
    __shared__ float red[256];
    const int b = blockIdx.x;
    const int tid = threadIdx.x;
    float vals[8];
    float mx = -INFINITY;
#pragma unroll
    for (int i = 0; i < 8; i++) {
        int s = tid + i * 256;
        float scv = g_scores[(size_t)b * SS + s];
        if (mask[(size_t)b * SS + s] == 0) scv = NEGV;
        vals[i] = scv;
        mx = fmaxf(mx, scv);
    }
    red[tid] = mx;
    __syncthreads();
    for (int off = 128; off >= 1; off >>= 1) {
        if (tid < off) red[tid] = fmaxf(red[tid], red[tid + off]);
        __syncthreads();
    }
    mx = red[0];
    __syncthreads();
    float sum = 0.f;
#pragma unroll
    for (int i = 0; i < 8; i++) {
        vals[i] = __expf(vals[i] - mx);
        sum += vals[i];
    }
    red[tid] = sum;
    __syncthreads();
    for (int off = 128; off >= 1; off >>= 1) {
        if (tid < off) red[tid] += red[tid + off];
        __syncthreads();
    }
    float inv = 1.f / red[0];
#pragma unroll
    for (int i = 0; i < 8; i++)
        out[(size_t)BB * DD + (size_t)b * SS + tid + i * 256] = vals[i] * inv;
}

// ---------------------------------------------------------------------------
// K4: context, 8 independent accumulators for MLP=8
// ---------------------------------------------------------------------------
__global__ __launch_bounds__(256) void context_kernel(
    const float* __restrict__ E, float* __restrict__ out) {
    __shared__ float a_s[SS];
    const int b = blockIdx.y;
    const int e = blockIdx.x * 256 + threadIdx.x;
    const float* attn = out + (size_t)BB * DD + (size_t)b * SS;
    for (int i = threadIdx.x; i < SS; i += 256) a_s[i] = attn[i];
    __syncthreads();
    const float* Ebe = E + (size_t)b * SS * DD + e;
    float c[8];
#pragma unroll
    for (int i = 0; i < 8; i++) c[i] = 0.f;
    for (int s0 = 0; s0 < SS; s0 += 8) {
#pragma unroll
        for (int i = 0; i < 8; i++)
            c[i] += a_s[s0 + i] * Ebe[(size_t)(s0 + i) * DD];
    }
    float r = ((c[0] + c[1]) + (c[2] + c[3])) + ((c[4] + c[5]) + (c[6] + c[7]));
    out[(size_t)b * DD + e] = r;
}

// ---------------------------------------------------------------------------
extern "C" void kernel_launch(void* const* d_in, const int* in_sizes, int n_in,
                              void* d_out, int out_size) {
    const float* dh   = (const float*)d_in[0];  // [64,1024]
    const float* E    = (const float*)d_in[1];  // [64,2048,1024]
    const int*   mask = (const int*)d_in[2];    // [64,2048]
    const float* Wenc = (const float*)d_in[3];  // [1024,1024]
    const float* Wdec = (const float*)d_in[4];  // [1024,1024]
    const float* v    = (const float*)d_in[5];  // [1024]
    float* out = (float*)d_out;                 // context [64,1024] ++ attn [64,2048]

    (void)cudaFuncSetAttribute(scores_v2,
                               cudaFuncAttributeMaxDynamicSharedMemorySize,
                               SMEM_TOTAL);

    dec_proj_kernel<<<DD / 64, 256>>>(dh, Wdec);
    dim3 g2(SS / 128, BB);
    scores_v2<<<g2, 256, SMEM_TOTAL>>>(E, Wenc, v);
    softmax_kernel<<<BB, 256>>>(mask, out);
    dim3 g4(DD / 256, BB);
    context_kernel<<<g4, 256>>>(E, out);
}

// round 7
// speedup vs baseline: 4.8819x; 2.0906x over previous
#include <cuda_runtime.h>
#include <cuda_bf16.h>
#include <math.h>
#include <stdint.h>

#define BB 64
#define SS 2048
#define DD 1024
#define NEGV (-1000000000.0f)

// ---------------- scratch (device globals; no allocations) ----------------
__device__ __nv_bfloat16 g_Ehi[(size_t)BB * SS * DD];
__device__ __nv_bfloat16 g_Elo[(size_t)BB * SS * DD];
__device__ __nv_bfloat16 g_Whi[DD * DD];
__device__ __nv_bfloat16 g_Wlo[DD * DD];
__device__ int g_idx[BB * SS];
__device__ int g_jof[BB * SS];
__device__ int g_cnt[BB];
__device__ int g_cntpad[BB];
__device__ float g_dec_proj[BB * DD];
__device__ float g_scores[BB * SS];
__device__ float g_attn_c[BB * SS];
__device__ float g_ctx_part[4][BB * DD];

// ---------------- helpers ----------------
__device__ __forceinline__ unsigned smem_u32(const void* p) {
    unsigned a;
    asm("{ .reg .u64 t; cvta.to.shared.u64 t, %1; cvt.u32.u64 %0, t; }"
        : "=r"(a) : "l"(p));
    return a;
}

__device__ __forceinline__ void ldsm4(unsigned r[4], unsigned addr) {
    asm volatile("ldmatrix.sync.aligned.m8n8.x4.shared.b16 {%0,%1,%2,%3}, [%4];"
                 : "=r"(r[0]), "=r"(r[1]), "=r"(r[2]), "=r"(r[3]) : "r"(addr));
}

__device__ __forceinline__ void mma16816(float c[4], const unsigned a[4],
                                         unsigned b0, unsigned b1) {
    asm volatile(
        "mma.sync.aligned.m16n8k16.row.col.f32.bf16.bf16.f32 "
        "{%0,%1,%2,%3},{%4,%5,%6,%7},{%8,%9},{%0,%1,%2,%3};"
        : "+f"(c[0]), "+f"(c[1]), "+f"(c[2]), "+f"(c[3])
        : "r"(a[0]), "r"(a[1]), "r"(a[2]), "r"(a[3]), "r"(b0), "r"(b1));
}

__device__ __forceinline__ float tanha(float x) {
    float y;
    asm("tanh.approx.f32 %0, %1;" : "=f"(y) : "f"(x));
    return y;
}

__device__ __forceinline__ void cp16(unsigned dst, const void* src) {
    asm volatile("cp.async.cg.shared.global [%0], [%1], 16;"
                 :: "r"(dst), "l"(src));
}
#define CP_COMMIT() asm volatile("cp.async.commit_group;" ::: "memory")

// split float4 into hi/lo bf16x4 (packed as uint2 each)
__device__ __forceinline__ void split4(float4 v, uint2& hi, uint2& lo) {
    unsigned hA, hB, lA, lB;
    asm("cvt.rn.bf16x2.f32 %0, %1, %2;" : "=r"(hA) : "f"(v.y), "f"(v.x));
    asm("cvt.rn.bf16x2.f32 %0, %1, %2;" : "=r"(hB) : "f"(v.w), "f"(v.z));
    float l0 = v.x - __uint_as_float(hA << 16);
    float l1 = v.y - __uint_as_float(hA & 0xffff0000u);
    float l2 = v.z - __uint_as_float(hB << 16);
    float l3 = v.w - __uint_as_float(hB & 0xffff0000u);
    asm("cvt.rn.bf16x2.f32 %0, %1, %2;" : "=r"(lA) : "f"(l1), "f"(l0));
    asm("cvt.rn.bf16x2.f32 %0, %1, %2;" : "=r"(lB) : "f"(l3), "f"(l2));
    hi.x = hA; hi.y = hB; lo.x = lA; lo.y = lB;
}

// ---------------------------------------------------------------------------
// K0a: per-b mask scan -> compact index list (deterministic, ascending s)
// ---------------------------------------------------------------------------
__global__ __launch_bounds__(256) void mask_scan(const int* __restrict__ mask) {
    __shared__ int wsum[8];
    __shared__ int wbase[8];
    const int b = blockIdx.x, tid = threadIdx.x;
    const int lane = tid & 31, w = tid >> 5;
    const int s0 = tid * 8;
    int m[8], tot = 0;
#pragma unroll
    for (int i = 0; i < 8; i++) {
        m[i] = (mask[b * SS + s0 + i] != 0);
        tot += m[i];
    }
    int inc = tot;
#pragma unroll
    for (int off = 1; off < 32; off <<= 1) {
        int t = __shfl_up_sync(0xffffffffu, inc, off);
        if (lane >= off) inc += t;
    }
    if (lane == 31) wsum[w] = inc;
    __syncthreads();
    if (tid == 0) {
        int r = 0;
#pragma unroll
        for (int k = 0; k < 8; k++) { wbase[k] = r; r += wsum[k]; }
        g_cnt[b] = r;
        g_cntpad[b] = (r + 127) & ~127;
    }
    __syncthreads();
    int run = wbase[w] + inc - tot;
#pragma unroll
    for (int i = 0; i < 8; i++) {
        if (m[i]) {
            g_idx[b * SS + run] = s0 + i;
            g_jof[b * SS + s0 + i] = run;
            run++;
        }
    }
}

// ---------------------------------------------------------------------------
// K0b: gather unmasked E rows + convert to bf16 hi/lo. Grid (S/8, B).
// ---------------------------------------------------------------------------
__global__ __launch_bounds__(256) void gather_convert(
    const float* __restrict__ E) {
    const int b = blockIdx.y;
    const int j0 = blockIdx.x * 8;
    const int cnt = g_cnt[b], cpad = g_cntpad[b];
    if (j0 >= cpad) return;
    const int r = threadIdx.x >> 5, lane = threadIdx.x & 31;
    const int j = j0 + r;
    const size_t dstoff = ((size_t)b * SS + j) * DD;
    if (j < cnt) {
        const int s = g_idx[b * SS + j];
        const float4* src = (const float4*)(E + ((size_t)b * SS + s) * DD);
#pragma unroll
        for (int i = 0; i < 8; i++) {
            const int c = lane + i * 32;  // float4 index (0..255)
            float4 v = src[c];
            uint2 hi, lo;
            split4(v, hi, lo);
            *(uint2*)(g_Ehi + dstoff + c * 4) = hi;
            *(uint2*)(g_Elo + dstoff + c * 4) = lo;
        }
    } else {
        uint2 z = {0u, 0u};
#pragma unroll
        for (int i = 0; i < 8; i++) {
            const int c = lane + i * 32;
            *(uint2*)(g_Ehi + dstoff + c * 4) = z;
            *(uint2*)(g_Elo + dstoff + c * 4) = z;
        }
    }
}

// K0c: W convert (1M elems). Grid 512 x 256.
__global__ __launch_bounds__(256) void wconv(const float* __restrict__ W) {
    const int t = blockIdx.x * 256 + threadIdx.x;  // 0..131071
    const size_t off = (size_t)t * 8;
#pragma unroll
    for (int i = 0; i < 2; i++) {
        float4 v = *(const float4*)(W + off + i * 4);
        uint2 hi, lo;
        split4(v, hi, lo);
        *(uint2*)(g_Whi + off + i * 4) = hi;
        *(uint2*)(g_Wlo + off + i * 4) = lo;
    }
}

// ---------------------------------------------------------------------------
// K1: dec_proj (SIMT, small)
// ---------------------------------------------------------------------------
__global__ __launch_bounds__(256) void dec_proj_kernel(
    const float* __restrict__ dh, const float* __restrict__ Wdec) {
    __shared__ float As[16][64];
    __shared__ float Bs[16][64];
    const int tid = threadIdx.x;
    const int d0 = blockIdx.x * 64;
    const int tx = tid % 16;
    const int ty = tid / 16;
    const int lrow = tid / 4;
    const int lk = (tid % 4) * 4;

    float acc[4][4];
#pragma unroll
    for (int i = 0; i < 4; i++)
#pragma unroll
        for (int j = 0; j < 4; j++) acc[i][j] = 0.f;

    for (int k0 = 0; k0 < DD; k0 += 16) {
        float4 av = *(const float4*)(dh + (size_t)lrow * DD + k0 + lk);
        float4 bv = *(const float4*)(Wdec + (size_t)(d0 + lrow) * DD + k0 + lk);
        __syncthreads();
        As[lk + 0][lrow] = av.x; As[lk + 1][lrow] = av.y;
        As[lk + 2][lrow] = av.z; As[lk + 3][lrow] = av.w;
        Bs[lk + 0][lrow] = bv.x; Bs[lk + 1][lrow] = bv.y;
        Bs[lk + 2][lrow] = bv.z; Bs[lk + 3][lrow] = bv.w;
        __syncthreads();
#pragma unroll
        for (int k = 0; k < 16; k++) {
            float a[4], bb[4];
#pragma unroll
            for (int i = 0; i < 4; i++) a[i] = As[k][ty * 4 + i];
#pragma unroll
            for (int j = 0; j < 4; j++) bb[j] = Bs[k][tx * 4 + j];
#pragma unroll
            for (int i = 0; i < 4; i++)
#pragma unroll
                for (int j = 0; j < 4; j++) acc[i][j] += a[i] * bb[j];
        }
    }
#pragma unroll
    for (int i = 0; i < 4; i++)
#pragma unroll
        for (int j = 0; j < 4; j++)
            g_dec_proj[(size_t)(ty * 4 + i) * DD + d0 + tx * 4 + j] = acc[i][j];
}

// ---------------------------------------------------------------------------
// K2 v4: pure mma.sync GEMM on pre-converted bf16 hi/lo, compacted rows.
// CTA: 128 s x 128 d per pass, 8 passes (d), k-chunks of 32, double-buffered
// cp.async.  Grid (S/128, B).  8 warps = 4 (m) x 2 (n).
// smem per buf: Ah,Al,Bh,Bl each 128 rows x 40 bf16 (pad) = 10240 B.
// ---------------------------------------------------------------------------
#define BUFB 40960
#define SCPO (2 * BUFB)          // 81920: scp[2][128] floats
#define SMEM_V4 (2 * BUFB + 1024)

__global__ __launch_bounds__(256, 2) void scores_v4(
    const float* __restrict__ v) {
    extern __shared__ char sm[];
    const unsigned sbase = smem_u32(sm);
    float* scp = (float*)(sm + SCPO);

    const int tid = threadIdx.x;
    const int lane = tid & 31, wid = tid >> 5;
    const int wm = wid & 3, wn = wid >> 2;
    const int g = lane >> 2, t4 = lane & 3;
    const int lm = lane >> 3, lr = lane & 7;
    const int b = blockIdx.y;
    const int s0 = blockIdx.x * 128;

    const int cnt = g_cnt[b];
    if (s0 >= g_cntpad[b]) return;

    if (tid < 256) { scp[tid] = 0.f; }

    const size_t eoff = ((size_t)b * SS + s0) * DD;
    const int grow = tid >> 2, gg4 = (tid & 3);  // granule mapping half 0
    // per-thread cp.async granule coords: h=0 -> (row=tid>>2, g4=tid&3)
    //                                     h=1 -> (row=64+(tid>>2), g4)

    float acc[2][8][4];

    // ---- software pipeline over it = pass*32 + kc  (256 iters) ----
    // issue(it): cp.async chunk into buf it&1
    auto issue = [&](int it) {
        const int pass = it >> 5, kc = it & 31;
        const unsigned d0 = sbase + (unsigned)(it & 1) * BUFB;
        const int koff = kc * 32;
        const size_t wo = (size_t)(pass * 128) * DD + koff;
        const size_t eo = eoff + koff;
#pragma unroll
        for (int h = 0; h < 2; h++) {
            const int row = grow + 64 * h;
            const unsigned dst = d0 + row * 80 + gg4 * 16;
            const size_t es = eo + (size_t)row * DD + gg4 * 8;
            const size_t ws = wo + (size_t)row * DD + gg4 * 8;
            cp16(dst,         g_Ehi + es);
            cp16(dst + 10240, g_Elo + es);
            cp16(dst + 20480, g_Whi + ws);
            cp16(dst + 30720, g_Wlo + ws);
        }
        CP_COMMIT();
    };

    issue(0);
    for (int it = 0; it < 256; it++) {
        if (it + 1 < 256) issue(it + 1);
        if (it + 1 < 256)
            asm volatile("cp.async.wait_group 1;" ::: "memory");
        else
            asm volatile("cp.async.wait_group 0;" ::: "memory");
        __syncthreads();

        if ((it & 31) == 0) {
#pragma unroll
            for (int mt = 0; mt < 2; mt++)
#pragma unroll
                for (int j = 0; j < 8; j++)
#pragma unroll
                    for (int c = 0; c < 4; c++) acc[mt][j][c] = 0.f;
        }

        const unsigned base = sbase + (unsigned)(it & 1) * BUFB;
        const unsigned ahb = base, alb = base + 10240;
        const unsigned bhb = base + 20480, blb = base + 30720;

#pragma unroll
        for (int kk = 0; kk < 2; kk++) {
            unsigned ah[2][4], al[2][4];
#pragma unroll
            for (int mt = 0; mt < 2; mt++) {
                const unsigned off =
                    (unsigned)((32 * wm + 16 * mt + (lm & 1) * 8 + lr) * 80 +
                               kk * 32 + (lm >> 1) * 16);
                ldsm4(ah[mt], ahb + off);
                ldsm4(al[mt], alb + off);
            }
#pragma unroll
            for (int j2 = 0; j2 < 4; j2++) {
                const unsigned boff =
                    (unsigned)((64 * wn + 8 * (2 * j2 + (lm >> 1)) + lr) * 80 +
                               kk * 32 + (lm & 1) * 16);
                unsigned bh[4], bl[4];
                ldsm4(bh, bhb + boff);
                ldsm4(bl, blb + boff);
#pragma unroll
                for (int jj = 0; jj < 2; jj++) {
                    const int j = 2 * j2 + jj;
#pragma unroll
                    for (int mt = 0; mt < 2; mt++) {
                        mma16816(acc[mt][j], ah[mt], bh[2 * jj], bh[2 * jj + 1]);
                        mma16816(acc[mt][j], ah[mt], bl[2 * jj], bl[2 * jj + 1]);
                        mma16816(acc[mt][j], al[mt], bh[2 * jj], bh[2 * jj + 1]);
                    }
                }
            }
        }

        if ((it & 31) == 31) {
            // epilogue for pass = it>>5 : tanh + v-dot
            const int pass = it >> 5;
            const float* dpb = g_dec_proj + (size_t)b * DD + pass * 128 + wn * 64;
            const float* vb = v + pass * 128 + wn * 64;
            float p[2][2] = {{0.f, 0.f}, {0.f, 0.f}};
#pragma unroll
            for (int mt = 0; mt < 2; mt++) {
#pragma unroll
                for (int j = 0; j < 8; j++) {
                    const int c0 = 8 * j + 2 * t4;
                    const float dp0 = dpb[c0], dp1 = dpb[c0 + 1];
                    const float v0 = vb[c0], v1 = vb[c0 + 1];
                    p[mt][0] += v0 * tanha(acc[mt][j][0] + dp0) +
                                v1 * tanha(acc[mt][j][1] + dp1);
                    p[mt][1] += v0 * tanha(acc[mt][j][2] + dp0) +
                                v1 * tanha(acc[mt][j][3] + dp1);
                }
            }
#pragma unroll
            for (int off = 1; off <= 2; off <<= 1)
#pragma unroll
                for (int mt = 0; mt < 2; mt++)
#pragma unroll
                    for (int rp = 0; rp < 2; rp++)
                        p[mt][rp] += __shfl_xor_sync(0xffffffffu, p[mt][rp], off);
            if (t4 == 0) {
#pragma unroll
                for (int mt = 0; mt < 2; mt++)
#pragma unroll
                    for (int rp = 0; rp < 2; rp++)
                        scp[wn * 128 + 32 * wm + 16 * mt + g + 8 * rp] +=
                            p[mt][rp];
            }
        }
        __syncthreads();
    }

    // scatter: compact row j = s0 + r -> original s = g_idx[b][j]
    if (tid < 128) {
        const int j = s0 + tid;
        if (j < cnt) {
            const int s = g_idx[b * SS + j];
            g_scores[b * SS + s] = scp[tid] + scp[128 + tid];
        }
    }
}

// ---------------------------------------------------------------------------
// K3: masked softmax; writes full attn to d_out and compact attn to g_attn_c
// ---------------------------------------------------------------------------
__global__ __launch_bounds__(256) void softmax_kernel(
    const int* __restrict__ mask, float* __restrict__ out) {
    __shared__ float red[256];
    const int b = blockIdx.x;
    const int tid = threadIdx.x;
    float vals[8];
    int msk[8];
    float mx = -INFINITY;
#pragma unroll
    for (int i = 0; i < 8; i++) {
        int s = tid + i * 256;
        size_t idx = (size_t)b * SS + s;
        msk[i] = (mask[idx] != 0);
        float scv = msk[i] ? g_scores[idx] : NEGV;
        vals[i] = scv;
        mx = fmaxf(mx, scv);
    }
    red[tid] = mx;
    __syncthreads();
    for (int off = 128; off >= 1; off >>= 1) {
        if (tid < off) red[tid] = fmaxf(red[tid], red[tid + off]);
        __syncthreads();
    }
    mx = red[0];
    __syncthreads();
    float sum = 0.f;
#pragma unroll
    for (int i = 0; i < 8; i++) {
        vals[i] = __expf(vals[i] - mx);
        sum += vals[i];
    }
    red[tid] = sum;
    __syncthreads();
    for (int off = 128; off >= 1; off >>= 1) {
        if (tid < off) red[tid] += red[tid + off];
        __syncthreads();
    }
    float inv = 1.f / red[0];
#pragma unroll
    for (int i = 0; i < 8; i++) {
        int s = tid + i * 256;
        size_t idx = (size_t)b * SS + s;
        float a = vals[i] * inv;
        out[(size_t)BB * DD + idx] = a;
        if (msk[i]) g_attn_c[(size_t)b * SS + g_jof[idx]] = a;
    }
}

// ---------------------------------------------------------------------------
// K4: context over compacted rows (bf16 hi+lo reconstruct). Grid (4,4,B).
// ---------------------------------------------------------------------------
__global__ __launch_bounds__(256) void context_part(const float* __restrict__ dummy) {
    __shared__ float a_s[512];
    const int b = blockIdx.z, sy = blockIdx.y;
    const int e = blockIdx.x * 256 + threadIdx.x;
    const int cnt = g_cnt[b];
    for (int i = threadIdx.x; i < 512; i += 256) {
        int j = sy * 512 + i;
        a_s[i] = (j < cnt) ? g_attn_c[(size_t)b * SS + j] : 0.f;
    }
    __syncthreads();
    const size_t base = ((size_t)b * SS + sy * 512) * DD + e;
    float c[4];
#pragma unroll
    for (int i = 0; i < 4; i++) c[i] = 0.f;
    for (int t = 0; t < 512; t += 4) {
#pragma unroll
        for (int i = 0; i < 4; i++) {
            float ev = __bfloat162float(g_Ehi[base + (size_t)(t + i) * DD]) +
                       __bfloat162float(g_Elo[base + (size_t)(t + i) * DD]);
            c[i] += a_s[t + i] * ev;
        }
    }
    g_ctx_part[sy][(size_t)b * DD + e] = (c[0] + c[1]) + (c[2] + c[3]);
}

__global__ __launch_bounds__(256) void ctx_reduce(float* __restrict__ out) {
    const int i = blockIdx.x * 256 + threadIdx.x;
    out[i] = (g_ctx_part[0][i] + g_ctx_part[1][i]) +
             (g_ctx_part[2][i] + g_ctx_part[3][i]);
}

// ---------------------------------------------------------------------------
extern "C" void kernel_launch(void* const* d_in, const int* in_sizes, int n_in,
                              void* d_out, int out_size) {
    const float* dh   = (const float*)d_in[0];  // [64,1024]
    const float* E    = (const float*)d_in[1];  // [64,2048,1024]
    const int*   mask = (const int*)d_in[2];    // [64,2048]
    const float* Wenc = (const float*)d_in[3];  // [1024,1024]
    const float* Wdec = (const float*)d_in[4];  // [1024,1024]
    const float* v    = (const float*)d_in[5];  // [1024]
    float* out = (float*)d_out;                 // context [64,1024] ++ attn [64,2048]

    (void)cudaFuncSetAttribute(scores_v4,
                               cudaFuncAttributeMaxDynamicSharedMemorySize,
                               SMEM_V4);

    mask_scan<<<BB, 256>>>(mask);
    dim3 gg(SS / 8, BB);
    gather_convert<<<gg, 256>>>(E);
    wconv<<<512, 256>>>(Wenc);
    dec_proj_kernel<<<DD / 64, 256>>>(dh, Wdec);
    dim3 g2(SS / 128, BB);
    scores_v4<<<g2, 256, SMEM_V4>>>(v);
    softmax_kernel<<<BB, 256>>>(mask, out);
    dim3 g4(4, 4, BB);
    context_part<<<g4, 256>>>(nullptr);
    ctx_reduce<<<BB * DD / 256, 256>>>(out);
}

// round 8
// speedup vs baseline: 5.0736x; 1.0393x over previous
#include <cuda_runtime.h>
#include <cuda_bf16.h>
#include <math.h>
#include <stdint.h>

#define BB 64
#define SS 2048
#define DD 1024
#define NEGV (-1000000000.0f)

// ---------------- scratch (device globals; no allocations) ----------------
__device__ float g_Ec[(size_t)BB * SS * DD];   // compacted, tf32-rounded E
__device__ float g_Wt[DD * DD];                // tf32-rounded W_enc
__device__ int g_idx[BB * SS];
__device__ int g_jof[BB * SS];
__device__ int g_cnt[BB];
__device__ int g_cntpad[BB];
__device__ float g_dec_proj[BB * DD];
__device__ float g_scores[BB * SS];
__device__ float g_attn_c[BB * SS];
__device__ float g_ctx_part[4][BB * DD];

// ---------------- helpers ----------------
__device__ __forceinline__ unsigned smem_u32(const void* p) {
    unsigned a;
    asm("{ .reg .u64 t; cvta.to.shared.u64 t, %1; cvt.u32.u64 %0, t; }"
        : "=r"(a) : "l"(p));
    return a;
}

__device__ __forceinline__ void ldsm4(unsigned r[4], unsigned addr) {
    asm volatile("ldmatrix.sync.aligned.m8n8.x4.shared.b16 {%0,%1,%2,%3}, [%4];"
                 : "=r"(r[0]), "=r"(r[1]), "=r"(r[2]), "=r"(r[3]) : "r"(addr));
}

__device__ __forceinline__ void mma_tf32(float c[4], const unsigned a[4],
                                         unsigned b0, unsigned b1) {
    asm volatile(
        "mma.sync.aligned.m16n8k8.row.col.f32.tf32.tf32.f32 "
        "{%0,%1,%2,%3},{%4,%5,%6,%7},{%8,%9},{%0,%1,%2,%3};"
        : "+f"(c[0]), "+f"(c[1]), "+f"(c[2]), "+f"(c[3])
        : "r"(a[0]), "r"(a[1]), "r"(a[2]), "r"(a[3]), "r"(b0), "r"(b1));
}

__device__ __forceinline__ float tanha(float x) {
    float y;
    asm("tanh.approx.f32 %0, %1;" : "=f"(y) : "f"(x));
    return y;
}

__device__ __forceinline__ float to_tf32(float x) {
    float y;
    asm("cvt.rna.tf32.f32 %0, %1;" : "=f"(y) : "f"(x));
    return y;
}

__device__ __forceinline__ void cp16(unsigned dst, const void* src) {
    asm volatile("cp.async.cg.shared.global [%0], [%1], 16;"
                 :: "r"(dst), "l"(src));
}
#define CP_COMMIT() asm volatile("cp.async.commit_group;" ::: "memory")

// ---------------------------------------------------------------------------
// K0a: per-b mask scan -> compact index list (deterministic, ascending s)
// ---------------------------------------------------------------------------
__global__ __launch_bounds__(256) void mask_scan(const int* __restrict__ mask) {
    __shared__ int wsum[8];
    __shared__ int wbase[8];
    const int b = blockIdx.x, tid = threadIdx.x;
    const int lane = tid & 31, w = tid >> 5;
    const int s0 = tid * 8;
    int m[8], tot = 0;
#pragma unroll
    for (int i = 0; i < 8; i++) {
        m[i] = (mask[b * SS + s0 + i] != 0);
        tot += m[i];
    }
    int inc = tot;
#pragma unroll
    for (int off = 1; off < 32; off <<= 1) {
        int t = __shfl_up_sync(0xffffffffu, inc, off);
        if (lane >= off) inc += t;
    }
    if (lane == 31) wsum[w] = inc;
    __syncthreads();
    if (tid == 0) {
        int r = 0;
#pragma unroll
        for (int k = 0; k < 8; k++) { wbase[k] = r; r += wsum[k]; }
        g_cnt[b] = r;
        g_cntpad[b] = (r + 127) & ~127;
    }
    __syncthreads();
    int run = wbase[w] + inc - tot;
#pragma unroll
    for (int i = 0; i < 8; i++) {
        if (m[i]) {
            g_idx[b * SS + run] = s0 + i;
            g_jof[b * SS + s0 + i] = run;
            run++;
        }
    }
}

// ---------------------------------------------------------------------------
// K0b: gather unmasked E rows, round to tf32. Grid (S/8, B).
// ---------------------------------------------------------------------------
__global__ __launch_bounds__(256) void gather_convert(
    const float* __restrict__ E) {
    const int b = blockIdx.y;
    const int j0 = blockIdx.x * 8;
    const int cnt = g_cnt[b], cpad = g_cntpad[b];
    if (j0 >= cpad) return;
    const int r = threadIdx.x >> 5, lane = threadIdx.x & 31;
    const int j = j0 + r;
    const size_t dstoff = ((size_t)b * SS + j) * DD;
    if (j < cnt) {
        const int s = g_idx[b * SS + j];
        const float4* src = (const float4*)(E + ((size_t)b * SS + s) * DD);
#pragma unroll
        for (int i = 0; i < 8; i++) {
            const int c = lane + i * 32;
            float4 vv = src[c];
            vv.x = to_tf32(vv.x); vv.y = to_tf32(vv.y);
            vv.z = to_tf32(vv.z); vv.w = to_tf32(vv.w);
            *(float4*)(g_Ec + dstoff + c * 4) = vv;
        }
    } else {
        float4 z = {0.f, 0.f, 0.f, 0.f};
#pragma unroll
        for (int i = 0; i < 8; i++)
            *(float4*)(g_Ec + dstoff + (lane + i * 32) * 4) = z;
    }
}

// K0c: W round to tf32. Grid 512 x 256.
__global__ __launch_bounds__(256) void wconv(const float* __restrict__ W) {
    const int t = blockIdx.x * 256 + threadIdx.x;
    const size_t off = (size_t)t * 8;
#pragma unroll
    for (int i = 0; i < 2; i++) {
        float4 vv = *(const float4*)(W + off + i * 4);
        vv.x = to_tf32(vv.x); vv.y = to_tf32(vv.y);
        vv.z = to_tf32(vv.z); vv.w = to_tf32(vv.w);
        *(float4*)(g_Wt + off + i * 4) = vv;
    }
}

// ---------------------------------------------------------------------------
// K1: dec_proj, warp-per-output. Grid 8192 x 256 (8 warps/block).
// ---------------------------------------------------------------------------
__global__ __launch_bounds__(256) void dec_proj_warp(
    const float* __restrict__ dh, const float* __restrict__ Wdec) {
    const int o = blockIdx.x * 8 + (threadIdx.x >> 5);  // 0..65535
    const int lane = threadIdx.x & 31;
    const int b = o >> 10, d = o & 1023;
    const float4* a = (const float4*)(dh + (size_t)b * DD);
    const float4* w = (const float4*)(Wdec + (size_t)d * DD);
    float s = 0.f;
#pragma unroll
    for (int i = 0; i < 8; i++) {
        float4 av = a[lane + i * 32];
        float4 wv = w[lane + i * 32];
        s += av.x * wv.x + av.y * wv.y + av.z * wv.z + av.w * wv.w;
    }
#pragma unroll
    for (int off = 16; off >= 1; off >>= 1)
        s += __shfl_xor_sync(0xffffffffu, s, off);
    if (lane == 0) g_dec_proj[o] = s;
}

// ---------------------------------------------------------------------------
// K2 v5: tf32 mma.sync GEMM on compacted rows.
// CTA 128 s x 128 d per pass, 8 passes, k-chunks of 32 (4 k8 steps),
// double-buffered cp.async. Grid (S/128, B). 8 warps = 4 (m) x 2 (n).
// smem tile: rows of 36 floats (144 B) -> ldmatrix conflict-free.
// ---------------------------------------------------------------------------
#define RSB 144                 // row stride bytes
#define TILEB (128 * RSB)       // 18432 per operand
#define BUFB (2 * TILEB)        // 36864 per stage (A + B)
#define SCPO (2 * BUFB)         // 73728
#define SMEM_V5 (2 * BUFB + 1024)

__global__ __launch_bounds__(256, 2) void scores_v5(
    const float* __restrict__ v) {
    extern __shared__ char sm[];
    const unsigned sbase = smem_u32(sm);
    float* scp = (float*)(sm + SCPO);

    const int tid = threadIdx.x;
    const int lane = tid & 31, wid = tid >> 5;
    const int wm = wid & 3, wn = wid >> 2;
    const int g = lane >> 2, t4 = lane & 3;
    const int b = blockIdx.y;
    const int s0 = blockIdx.x * 128;

    const int cnt = g_cnt[b];
    if (s0 >= g_cntpad[b]) return;

    scp[tid] = 0.f;

    const size_t eoff = ((size_t)b * SS + s0) * DD;
    const int crow = tid >> 1;            // 0..127
    const int chalf = (tid & 1) * 16;     // float offset within row

    float acc[2][8][4];

    auto issue = [&](int it) {
        const int pass = it >> 5, kc = it & 31;
        const unsigned d0 = sbase + (unsigned)(it & 1) * BUFB;
        const int koff = kc * 32;
        const size_t es = eoff + (size_t)crow * DD + koff + chalf;
        const size_t ws = (size_t)(pass * 128 + crow) * DD + koff + chalf;
        const unsigned dst = d0 + crow * RSB + chalf * 4;
#pragma unroll
        for (int i = 0; i < 4; i++) {
            cp16(dst + i * 16,         g_Ec + es + i * 4);
            cp16(dst + TILEB + i * 16, g_Wt + ws + i * 4);
        }
        CP_COMMIT();
    };

    // ldmatrix lane-tile coords
    const int lt = lane >> 3, lr = lane & 7;

    issue(0);
    for (int it = 0; it < 256; it++) {
        if (it + 1 < 256) issue(it + 1);
        if (it + 1 < 256)
            asm volatile("cp.async.wait_group 1;" ::: "memory");
        else
            asm volatile("cp.async.wait_group 0;" ::: "memory");
        __syncthreads();

        if ((it & 31) == 0) {
#pragma unroll
            for (int mt = 0; mt < 2; mt++)
#pragma unroll
                for (int j = 0; j < 8; j++)
#pragma unroll
                    for (int c = 0; c < 4; c++) acc[mt][j][c] = 0.f;
        }

        const unsigned abase = sbase + (unsigned)(it & 1) * BUFB;
        const unsigned bbase = abase + TILEB;

#pragma unroll
        for (int ks = 0; ks < 4; ks++) {
            // A fragments: tiles (rows R+(lt&1)*8, k4 = ks*8 + (lt>>1)*4)
            unsigned ah[2][4];
#pragma unroll
            for (int mt = 0; mt < 2; mt++) {
                const int row = 32 * wm + 16 * mt + (lt & 1) * 8 + lr;
                const int c4 = ks * 8 + (lt >> 1) * 4;
                ldsm4(ah[mt], abase + row * RSB + c4 * 4);
            }
#pragma unroll
            for (int j2 = 0; j2 < 4; j2++) {
                // B tiles: (n-group 2*j2 + (lt>>1), k half lt&1)
                const int nrow = 64 * wn + 8 * (2 * j2 + (lt >> 1)) + lr;
                const int c4 = ks * 8 + (lt & 1) * 4;
                unsigned bb[4];
                ldsm4(bb, bbase + nrow * RSB + c4 * 4);
#pragma unroll
                for (int jj = 0; jj < 2; jj++) {
                    const int j = 2 * j2 + jj;
#pragma unroll
                    for (int mt = 0; mt < 2; mt++)
                        mma_tf32(acc[mt][j], ah[mt], bb[2 * jj], bb[2 * jj + 1]);
                }
            }
        }

        if ((it & 31) == 31) {
            const int pass = it >> 5;
            const float* dpb = g_dec_proj + (size_t)b * DD + pass * 128 + wn * 64;
            const float* vb = v + pass * 128 + wn * 64;
            float p[2][2] = {{0.f, 0.f}, {0.f, 0.f}};
#pragma unroll
            for (int mt = 0; mt < 2; mt++) {
#pragma unroll
                for (int j = 0; j < 8; j++) {
                    const int c0 = 8 * j + 2 * t4;
                    const float dp0 = dpb[c0], dp1 = dpb[c0 + 1];
                    const float v0 = vb[c0], v1 = vb[c0 + 1];
                    p[mt][0] += v0 * tanha(acc[mt][j][0] + dp0) +
                                v1 * tanha(acc[mt][j][1] + dp1);
                    p[mt][1] += v0 * tanha(acc[mt][j][2] + dp0) +
                                v1 * tanha(acc[mt][j][3] + dp1);
                }
            }
#pragma unroll
            for (int off = 1; off <= 2; off <<= 1)
#pragma unroll
                for (int mt = 0; mt < 2; mt++)
#pragma unroll
                    for (int rp = 0; rp < 2; rp++)
                        p[mt][rp] += __shfl_xor_sync(0xffffffffu, p[mt][rp], off);
            if (t4 == 0) {
#pragma unroll
                for (int mt = 0; mt < 2; mt++)
#pragma unroll
                    for (int rp = 0; rp < 2; rp++)
                        scp[wn * 128 + 32 * wm + 16 * mt + g + 8 * rp] +=
                            p[mt][rp];
            }
        }
        __syncthreads();
    }

    if (tid < 128) {
        const int j = s0 + tid;
        if (j < cnt) {
            const int s = g_idx[b * SS + j];
            g_scores[b * SS + s] = scp[tid] + scp[128 + tid];
        }
    }
}

// ---------------------------------------------------------------------------
// K3: masked softmax; full attn to d_out, compact attn to g_attn_c
// ---------------------------------------------------------------------------
__global__ __launch_bounds__(256) void softmax_kernel(
    const int* __restrict__ mask, float* __restrict__ out) {
    __shared__ float red[256];
    const int b = blockIdx.x;
    const int tid = threadIdx.x;
    float vals[8];
    int msk[8];
    float mx = -INFINITY;
#pragma unroll
    for (int i = 0; i < 8; i++) {
        int s = tid + i * 256;
        size_t idx = (size_t)b * SS + s;
        msk[i] = (mask[idx] != 0);
        float scv = msk[i] ? g_scores[idx] : NEGV;
        vals[i] = scv;
        mx = fmaxf(mx, scv);
    }
    red[tid] = mx;
    __syncthreads();
    for (int off = 128; off >= 1; off >>= 1) {
        if (tid < off) red[tid] = fmaxf(red[tid], red[tid + off]);
        __syncthreads();
    }
    mx = red[0];
    __syncthreads();
    float sum = 0.f;
#pragma unroll
    for (int i = 0; i < 8; i++) {
        vals[i] = __expf(vals[i] - mx);
        sum += vals[i];
    }
    red[tid] = sum;
    __syncthreads();
    for (int off = 128; off >= 1; off >>= 1) {
        if (tid < off) red[tid] += red[tid + off];
        __syncthreads();
    }
    float inv = 1.f / red[0];
#pragma unroll
    for (int i = 0; i < 8; i++) {
        int s = tid + i * 256;
        size_t idx = (size_t)b * SS + s;
        float a = vals[i] * inv;
        out[(size_t)BB * DD + idx] = a;
        if (msk[i]) g_attn_c[(size_t)b * SS + g_jof[idx]] = a;
    }
}

// ---------------------------------------------------------------------------
// K4: context over compacted rows. Grid (4,4,B).
// ---------------------------------------------------------------------------
__global__ __launch_bounds__(256) void context_part() {
    __shared__ float a_s[512];
    const int b = blockIdx.z, sy = blockIdx.y;
    const int e = blockIdx.x * 256 + threadIdx.x;
    const int cnt = g_cnt[b];
    for (int i = threadIdx.x; i < 512; i += 256) {
        int j = sy * 512 + i;
        a_s[i] = (j < cnt) ? g_attn_c[(size_t)b * SS + j] : 0.f;
    }
    __syncthreads();
    const size_t base = ((size_t)b * SS + sy * 512) * DD + e;
    float c[4];
#pragma unroll
    for (int i = 0; i < 4; i++) c[i] = 0.f;
    for (int t = 0; t < 512; t += 4) {
#pragma unroll
        for (int i = 0; i < 4; i++)
            c[i] += a_s[t + i] * g_Ec[base + (size_t)(t + i) * DD];
    }
    g_ctx_part[sy][(size_t)b * DD + e] = (c[0] + c[1]) + (c[2] + c[3]);
}

__global__ __launch_bounds__(256) void ctx_reduce(float* __restrict__ out) {
    const int i = blockIdx.x * 256 + threadIdx.x;
    out[i] = (g_ctx_part[0][i] + g_ctx_part[1][i]) +
             (g_ctx_part[2][i] + g_ctx_part[3][i]);
}

// ---------------------------------------------------------------------------
extern "C" void kernel_launch(void* const* d_in, const int* in_sizes, int n_in,
                              void* d_out, int out_size) {
    const float* dh   = (const float*)d_in[0];  // [64,1024]
    const float* E    = (const float*)d_in[1];  // [64,2048,1024]
    const int*   mask = (const int*)d_in[2];    // [64,2048]
    const float* Wenc = (const float*)d_in[3];  // [1024,1024]
    const float* Wdec = (const float*)d_in[4];  // [1024,1024]
    const float* v    = (const float*)d_in[5];  // [1024]
    float* out = (float*)d_out;                 // context [64,1024] ++ attn [64,2048]

    (void)cudaFuncSetAttribute(scores_v5,
                               cudaFuncAttributeMaxDynamicSharedMemorySize,
                               SMEM_V5);

    mask_scan<<<BB, 256>>>(mask);
    dim3 gg(SS / 8, BB);
    gather_convert<<<gg, 256>>>(E);
    wconv<<<512, 256>>>(Wenc);
    dec_proj_warp<<<BB * DD / 8, 256>>>(dh, Wdec);
    dim3 g2(SS / 128, BB);
    scores_v5<<<g2, 256, SMEM_V5>>>(v);
    softmax_kernel<<<BB, 256>>>(mask, out);
    dim3 g4(4, 4, BB);
    context_part<<<g4, 256>>>();
    ctx_reduce<<<BB * DD / 256, 256>>>(out);
}

// round 9
// speedup vs baseline: 5.1686x; 1.0187x over previous
#include <cuda_runtime.h>
#include <cuda_bf16.h>
#include <math.h>
#include <stdint.h>

#define BB 64
#define SS 2048
#define DD 1024
#define NEGV (-1000000000.0f)

// ---------------- scratch (device globals; no allocations) ----------------
__device__ float g_Ec[(size_t)BB * SS * DD];   // compacted, tf32-rounded E
__device__ float g_Wt[DD * DD];                // tf32-rounded W_enc
__device__ int g_idx[BB * SS];
__device__ int g_jof[BB * SS];
__device__ int g_cnt[BB];
__device__ int g_cntpad[BB];
__device__ float g_dec_proj[BB * DD];
__device__ float g_scores[BB * SS];
__device__ float g_attn_c[BB * SS];
__device__ float g_ctx_part[4][BB * DD];

// ---------------- helpers ----------------
__device__ __forceinline__ unsigned smem_u32(const void* p) {
    unsigned a;
    asm("{ .reg .u64 t; cvta.to.shared.u64 t, %1; cvt.u32.u64 %0, t; }"
        : "=r"(a) : "l"(p));
    return a;
}

__device__ __forceinline__ void ldsm4(unsigned r[4], unsigned addr) {
    asm volatile("ldmatrix.sync.aligned.m8n8.x4.shared.b16 {%0,%1,%2,%3}, [%4];"
                 : "=r"(r[0]), "=r"(r[1]), "=r"(r[2]), "=r"(r[3]) : "r"(addr));
}

__device__ __forceinline__ void mma_tf32(float c[4], const unsigned a[4],
                                         unsigned b0, unsigned b1) {
    asm volatile(
        "mma.sync.aligned.m16n8k8.row.col.f32.tf32.tf32.f32 "
        "{%0,%1,%2,%3},{%4,%5,%6,%7},{%8,%9},{%0,%1,%2,%3};"
        : "+f"(c[0]), "+f"(c[1]), "+f"(c[2]), "+f"(c[3])
        : "r"(a[0]), "r"(a[1]), "r"(a[2]), "r"(a[3]), "r"(b0), "r"(b1));
}

__device__ __forceinline__ float tanha(float x) {
    float y;
    asm("tanh.approx.f32 %0, %1;" : "=f"(y) : "f"(x));
    return y;
}

__device__ __forceinline__ float to_tf32(float x) {
    float y;
    asm("cvt.rna.tf32.f32 %0, %1;" : "=f"(y) : "f"(x));
    return y;
}

__device__ __forceinline__ void cp16(unsigned dst, const void* src) {
    asm volatile("cp.async.cg.shared.global [%0], [%1], 16;"
                 :: "r"(dst), "l"(src));
}
#define CP_COMMIT() asm volatile("cp.async.commit_group;" ::: "memory")

// ---------------------------------------------------------------------------
// K0a: per-b mask scan -> compact index list (deterministic, ascending s)
// ---------------------------------------------------------------------------
__global__ __launch_bounds__(256) void mask_scan(const int* __restrict__ mask) {
    __shared__ int wsum[8];
    __shared__ int wbase[8];
    const int b = blockIdx.x, tid = threadIdx.x;
    const int lane = tid & 31, w = tid >> 5;
    const int s0 = tid * 8;
    int m[8], tot = 0;
#pragma unroll
    for (int i = 0; i < 8; i++) {
        m[i] = (mask[b * SS + s0 + i] != 0);
        tot += m[i];
    }
    int inc = tot;
#pragma unroll
    for (int off = 1; off < 32; off <<= 1) {
        int t = __shfl_up_sync(0xffffffffu, inc, off);
        if (lane >= off) inc += t;
    }
    if (lane == 31) wsum[w] = inc;
    __syncthreads();
    if (tid == 0) {
        int r = 0;
#pragma unroll
        for (int k = 0; k < 8; k++) { wbase[k] = r; r += wsum[k]; }
        g_cnt[b] = r;
        g_cntpad[b] = (r + 127) & ~127;
    }
    __syncthreads();
    int run = wbase[w] + inc - tot;
#pragma unroll
    for (int i = 0; i < 8; i++) {
        if (m[i]) {
            g_idx[b * SS + run] = s0 + i;
            g_jof[b * SS + s0 + i] = run;
            run++;
        }
    }
}

// ---------------------------------------------------------------------------
// K0b: gather unmasked E rows, round to tf32. Grid (S/8, B).
// ---------------------------------------------------------------------------
__global__ __launch_bounds__(256) void gather_convert(
    const float* __restrict__ E) {
    const int b = blockIdx.y;
    const int j0 = blockIdx.x * 8;
    const int cnt = g_cnt[b], cpad = g_cntpad[b];
    if (j0 >= cpad) return;
    const int r = threadIdx.x >> 5, lane = threadIdx.x & 31;
    const int j = j0 + r;
    const size_t dstoff = ((size_t)b * SS + j) * DD;
    if (j < cnt) {
        const int s = g_idx[b * SS + j];
        const float4* src = (const float4*)(E + ((size_t)b * SS + s) * DD);
#pragma unroll
        for (int i = 0; i < 8; i++) {
            const int c = lane + i * 32;
            float4 vv = src[c];
            vv.x = to_tf32(vv.x); vv.y = to_tf32(vv.y);
            vv.z = to_tf32(vv.z); vv.w = to_tf32(vv.w);
            *(float4*)(g_Ec + dstoff + c * 4) = vv;
        }
    } else {
        float4 z = {0.f, 0.f, 0.f, 0.f};
#pragma unroll
        for (int i = 0; i < 8; i++)
            *(float4*)(g_Ec + dstoff + (lane + i * 32) * 4) = z;
    }
}

// K0c: W round to tf32. Grid 512 x 256.
__global__ __launch_bounds__(256) void wconv(const float* __restrict__ W) {
    const int t = blockIdx.x * 256 + threadIdx.x;
    const size_t off = (size_t)t * 8;
#pragma unroll
    for (int i = 0; i < 2; i++) {
        float4 vv = *(const float4*)(W + off + i * 4);
        vv.x = to_tf32(vv.x); vv.y = to_tf32(vv.y);
        vv.z = to_tf32(vv.z); vv.w = to_tf32(vv.w);
        *(float4*)(g_Wt + off + i * 4) = vv;
    }
}

// ---------------------------------------------------------------------------
// K1: dec_proj, warp-per-output. Grid 8192 x 256 (8 warps/block).
// ---------------------------------------------------------------------------
__global__ __launch_bounds__(256) void dec_proj_warp(
    const float* __restrict__ dh, const float* __restrict__ Wdec) {
    const int o = blockIdx.x * 8 + (threadIdx.x >> 5);  // 0..65535
    const int lane = threadIdx.x & 31;
    const int b = o >> 10, d = o & 1023;
    const float4* a = (const float4*)(dh + (size_t)b * DD);
    const float4* w = (const float4*)(Wdec + (size_t)d * DD);
    float s = 0.f;
#pragma unroll
    for (int i = 0; i < 8; i++) {
        float4 av = a[lane + i * 32];
        float4 wv = w[lane + i * 32];
        s += av.x * wv.x + av.y * wv.y + av.z * wv.z + av.w * wv.w;
    }
#pragma unroll
    for (int off = 16; off >= 1; off >>= 1)
        s += __shfl_xor_sync(0xffffffffu, s, off);
    if (lane == 0) g_dec_proj[o] = s;
}

// ---------------------------------------------------------------------------
// K2 v6: tf32 mma.sync GEMM, 3-stage cp.async pipeline, 1 sync per iter.
// CTA 128 s x 128 d per pass, 8 passes, k-chunks of 32 (4 k8 steps).
// Grid (S/128, B). 8 warps = 4 (m) x 2 (n). Row stride 36 floats.
// ---------------------------------------------------------------------------
#define RSB 144                 // row stride bytes (36 floats)
#define TILEB (128 * RSB)       // 18432 per operand
#define BUFB (2 * TILEB)        // 36864 per stage (A + B)
#define NSTAGE 3
#define SCPO (NSTAGE * BUFB)    // 110592
#define SMEM_V6 (NSTAGE * BUFB + 1024)

__global__ __launch_bounds__(256, 2) void scores_v6(
    const float* __restrict__ v) {
    extern __shared__ char sm[];
    const unsigned sbase = smem_u32(sm);
    float* scp = (float*)(sm + SCPO);

    const int tid = threadIdx.x;
    const int lane = tid & 31, wid = tid >> 5;
    const int wm = wid & 3, wn = wid >> 2;
    const int g = lane >> 2, t4 = lane & 3;
    const int b = blockIdx.y;
    const int s0 = blockIdx.x * 128;

    const int cnt = g_cnt[b];
    if (s0 >= g_cntpad[b]) return;

    scp[tid] = 0.f;

    const size_t eoff = ((size_t)b * SS + s0) * DD;
    const int crow = tid >> 1;            // 0..127
    const int chalf = (tid & 1) * 16;     // float offset within row

    float acc[2][8][4];

    auto issue = [&](int it) {
        const int pass = it >> 5, kc = it & 31;
        const unsigned d0 = sbase + (unsigned)(it % NSTAGE) * BUFB;
        const int koff = kc * 32;
        const size_t es = eoff + (size_t)crow * DD + koff + chalf;
        const size_t ws = (size_t)(pass * 128 + crow) * DD + koff + chalf;
        const unsigned dst = d0 + crow * RSB + chalf * 4;
#pragma unroll
        for (int i = 0; i < 4; i++) {
            cp16(dst + i * 16,         g_Ec + es + i * 4);
            cp16(dst + TILEB + i * 16, g_Wt + ws + i * 4);
        }
        CP_COMMIT();
    };

    const int lt = lane >> 3, lr = lane & 7;

    issue(0);
    issue(1);
    for (int it = 0; it < 256; it++) {
        asm volatile("cp.async.wait_group 1;" ::: "memory");
        __syncthreads();
        if (it + 2 < 256) issue(it + 2);

        if ((it & 31) == 0) {
#pragma unroll
            for (int mt = 0; mt < 2; mt++)
#pragma unroll
                for (int j = 0; j < 8; j++)
#pragma unroll
                    for (int c = 0; c < 4; c++) acc[mt][j][c] = 0.f;
        }

        const unsigned abase = sbase + (unsigned)(it % NSTAGE) * BUFB;
        const unsigned bbase = abase + TILEB;

#pragma unroll
        for (int ks = 0; ks < 4; ks++) {
            unsigned ah[2][4];
#pragma unroll
            for (int mt = 0; mt < 2; mt++) {
                const int row = 32 * wm + 16 * mt + (lt & 1) * 8 + lr;
                const int c4 = ks * 8 + (lt >> 1) * 4;
                ldsm4(ah[mt], abase + row * RSB + c4 * 4);
            }
#pragma unroll
            for (int j2 = 0; j2 < 4; j2++) {
                const int nrow = 64 * wn + 8 * (2 * j2 + (lt >> 1)) + lr;
                const int c4 = ks * 8 + (lt & 1) * 4;
                unsigned bb[4];
                ldsm4(bb, bbase + nrow * RSB + c4 * 4);
#pragma unroll
                for (int jj = 0; jj < 2; jj++) {
                    const int j = 2 * j2 + jj;
#pragma unroll
                    for (int mt = 0; mt < 2; mt++)
                        mma_tf32(acc[mt][j], ah[mt], bb[2 * jj], bb[2 * jj + 1]);
                }
            }
        }

        if ((it & 31) == 31) {
            const int pass = it >> 5;
            const float* dpb = g_dec_proj + (size_t)b * DD + pass * 128 + wn * 64;
            const float* vb = v + pass * 128 + wn * 64;
            float p[2][2] = {{0.f, 0.f}, {0.f, 0.f}};
#pragma unroll
            for (int mt = 0; mt < 2; mt++) {
#pragma unroll
                for (int j = 0; j < 8; j++) {
                    const int c0 = 8 * j + 2 * t4;
                    const float dp0 = dpb[c0], dp1 = dpb[c0 + 1];
                    const float v0 = vb[c0], v1 = vb[c0 + 1];
                    p[mt][0] += v0 * tanha(acc[mt][j][0] + dp0) +
                                v1 * tanha(acc[mt][j][1] + dp1);
                    p[mt][1] += v0 * tanha(acc[mt][j][2] + dp0) +
                                v1 * tanha(acc[mt][j][3] + dp1);
                }
            }
#pragma unroll
            for (int off = 1; off <= 2; off <<= 1)
#pragma unroll
                for (int mt = 0; mt < 2; mt++)
#pragma unroll
                    for (int rp = 0; rp < 2; rp++)
                        p[mt][rp] += __shfl_xor_sync(0xffffffffu, p[mt][rp], off);
            // scp locations are exclusive per warp: no barrier needed
            if (t4 == 0) {
#pragma unroll
                for (int mt = 0; mt < 2; mt++)
#pragma unroll
                    for (int rp = 0; rp < 2; rp++)
                        scp[wn * 128 + 32 * wm + 16 * mt + g + 8 * rp] +=
                            p[mt][rp];
            }
        }
    }

    __syncthreads();
    if (tid < 128) {
        const int j = s0 + tid;
        if (j < cnt) {
            const int s = g_idx[b * SS + j];
            g_scores[b * SS + s] = scp[tid] + scp[128 + tid];
        }
    }
}

// ---------------------------------------------------------------------------
// K3: masked softmax; full attn to d_out, compact attn to g_attn_c
// ---------------------------------------------------------------------------
__global__ __launch_bounds__(256) void softmax_kernel(
    const int* __restrict__ mask, float* __restrict__ out) {
    __shared__ float red[256];
    const int b = blockIdx.x;
    const int tid = threadIdx.x;
    float vals[8];
    int msk[8];
    float mx = -INFINITY;
#pragma unroll
    for (int i = 0; i < 8; i++) {
        int s = tid + i * 256;
        size_t idx = (size_t)b * SS + s;
        msk[i] = (mask[idx] != 0);
        float scv = msk[i] ? g_scores[idx] : NEGV;
        vals[i] = scv;
        mx = fmaxf(mx, scv);
    }
    red[tid] = mx;
    __syncthreads();
    for (int off = 128; off >= 1; off >>= 1) {
        if (tid < off) red[tid] = fmaxf(red[tid], red[tid + off]);
        __syncthreads();
    }
    mx = red[0];
    __syncthreads();
    float sum = 0.f;
#pragma unroll
    for (int i = 0; i < 8; i++) {
        vals[i] = __expf(vals[i] - mx);
        sum += vals[i];
    }
    red[tid] = sum;
    __syncthreads();
    for (int off = 128; off >= 1; off >>= 1) {
        if (tid < off) red[tid] += red[tid + off];
        __syncthreads();
    }
    float inv = 1.f / red[0];
#pragma unroll
    for (int i = 0; i < 8; i++) {
        int s = tid + i * 256;
        size_t idx = (size_t)b * SS + s;
        float a = vals[i] * inv;
        out[(size_t)BB * DD + idx] = a;
        if (msk[i]) g_attn_c[(size_t)b * SS + g_jof[idx]] = a;
    }
}

// ---------------------------------------------------------------------------
// K4: context over compacted rows. Grid (4,4,B).
// ---------------------------------------------------------------------------
__global__ __launch_bounds__(256) void context_part() {
    __shared__ float a_s[512];
    const int b = blockIdx.z, sy = blockIdx.y;
    const int e = blockIdx.x * 256 + threadIdx.x;
    const int cnt = g_cnt[b];
    for (int i = threadIdx.x; i < 512; i += 256) {
        int j = sy * 512 + i;
        a_s[i] = (j < cnt) ? g_attn_c[(size_t)b * SS + j] : 0.f;
    }
    __syncthreads();
    const size_t base = ((size_t)b * SS + sy * 512) * DD + e;
    float c[4];
#pragma unroll
    for (int i = 0; i < 4; i++) c[i] = 0.f;
    for (int t = 0; t < 512; t += 4) {
#pragma unroll
        for (int i = 0; i < 4; i++)
            c[i] += a_s[t + i] * g_Ec[base + (size_t)(t + i) * DD];
    }
    g_ctx_part[sy][(size_t)b * DD + e] = (c[0] + c[1]) + (c[2] + c[3]);
}

__global__ __launch_bounds__(256) void ctx_reduce(float* __restrict__ out) {
    const int i = blockIdx.x * 256 + threadIdx.x;
    out[i] = (g_ctx_part[0][i] + g_ctx_part[1][i]) +
             (g_ctx_part[2][i] + g_ctx_part[3][i]);
}

// ---------------------------------------------------------------------------
extern "C" void kernel_launch(void* const* d_in, const int* in_sizes, int n_in,
                              void* d_out, int out_size) {
    const float* dh   = (const float*)d_in[0];  // [64,1024]
    const float* E    = (const float*)d_in[1];  // [64,2048,1024]
    const int*   mask = (const int*)d_in[2];    // [64,2048]
    const float* Wenc = (const float*)d_in[3];  // [1024,1024]
    const float* Wdec = (const float*)d_in[4];  // [1024,1024]
    const float* v    = (const float*)d_in[5];  // [1024]
    float* out = (float*)d_out;                 // context [64,1024] ++ attn [64,2048]

    (void)cudaFuncSetAttribute(scores_v6,
                               cudaFuncAttributeMaxDynamicSharedMemorySize,
                               SMEM_V6);

    mask_scan<<<BB, 256>>>(mask);
    dim3 gg(SS / 8, BB);
    gather_convert<<<gg, 256>>>(E);
    wconv<<<512, 256>>>(Wenc);
    dec_proj_warp<<<BB * DD / 8, 256>>>(dh, Wdec);
    dim3 g2(SS / 128, BB);
    scores_v6<<<g2, 256, SMEM_V6>>>(v);
    softmax_kernel<<<BB, 256>>>(mask, out);
    dim3 g4(4, 4, BB);
    context_part<<<g4, 256>>>();
    ctx_reduce<<<BB * DD / 256, 256>>>(out);
}

// round 14
// speedup vs baseline: 9.4636x; 1.8310x over previous
#include <cuda_runtime.h>
#include <cuda_fp16.h>
#include <math.h>
#include <stdint.h>

#define BB 64
#define SS 2048
#define DD 1024
#define NEGV (-1000000000.0f)

// ---------------- scratch (device globals; no allocations) ----------------
__device__ __half g_Ech[(size_t)BB * SS * DD];  // compacted fp16 E
__device__ __half g_Wh[DD * DD];                // fp16 W_enc
__device__ int g_idx[BB * SS];
__device__ int g_jof[BB * SS];
__device__ int g_cnt[BB];
__device__ int g_cntpad[BB];
__device__ float g_dec_proj[BB * DD];
__device__ float g_scores[BB * SS];
__device__ float g_attn_c[BB * SS];
__device__ float g_ctx_part[4][BB * DD];

// ---------------- helpers ----------------
__device__ __forceinline__ unsigned smem_u32(const void* p) {
    unsigned a;
    asm("{ .reg .u64 t; cvta.to.shared.u64 t, %1; cvt.u32.u64 %0, t; }"
        : "=r"(a) : "l"(p));
    return a;
}

__device__ __forceinline__ void ldsm4(unsigned r[4], unsigned addr) {
    asm volatile("ldmatrix.sync.aligned.m8n8.x4.shared.b16 {%0,%1,%2,%3}, [%4];"
                 : "=r"(r[0]), "=r"(r[1]), "=r"(r[2]), "=r"(r[3]) : "r"(addr));
}

__device__ __forceinline__ void mma_f16(float c[4], const unsigned a[4],
                                        unsigned b0, unsigned b1) {
    asm volatile(
        "mma.sync.aligned.m16n8k16.row.col.f32.f16.f16.f32 "
        "{%0,%1,%2,%3},{%4,%5,%6,%7},{%8,%9},{%0,%1,%2,%3};"
        : "+f"(c[0]), "+f"(c[1]), "+f"(c[2]), "+f"(c[3])
        : "r"(a[0]), "r"(a[1]), "r"(a[2]), "r"(a[3]), "r"(b0), "r"(b1));
}

__device__ __forceinline__ float tanha(float x) {
    float y;
    asm("tanh.approx.f32 %0, %1;" : "=f"(y) : "f"(x));
    return y;
}

__device__ __forceinline__ void cp16(unsigned dst, const void* src) {
    asm volatile("cp.async.cg.shared.global [%0], [%1], 16;"
                 :: "r"(dst), "l"(src));
}
#define CP_COMMIT() asm volatile("cp.async.commit_group;" ::: "memory")

// pack float4 -> 4 fp16 (uint2)
__device__ __forceinline__ uint2 pack_h4(float4 v) {
    uint2 r;
    asm("{ .reg .b16 a, b; cvt.rn.f16.f32 a, %1; cvt.rn.f16.f32 b, %2;"
        "  mov.b32 %0, {a, b}; }" : "=r"(r.x) : "f"(v.x), "f"(v.y));
    asm("{ .reg .b16 a, b; cvt.rn.f16.f32 a, %1; cvt.rn.f16.f32 b, %2;"
        "  mov.b32 %0, {a, b}; }" : "=r"(r.y) : "f"(v.z), "f"(v.w));
    return r;
}

// ---------------------------------------------------------------------------
// K0a: per-b mask scan -> compact index list (deterministic, ascending s)
// ---------------------------------------------------------------------------
__global__ __launch_bounds__(256) void mask_scan(const int* __restrict__ mask) {
    __shared__ int wsum[8];
    __shared__ int wbase[8];
    const int b = blockIdx.x, tid = threadIdx.x;
    const int lane = tid & 31, w = tid >> 5;
    const int s0 = tid * 8;
    int m[8], tot = 0;
#pragma unroll
    for (int i = 0; i < 8; i++) {
        m[i] = (mask[b * SS + s0 + i] != 0);
        tot += m[i];
    }
    int inc = tot;
#pragma unroll
    for (int off = 1; off < 32; off <<= 1) {
        int t = __shfl_up_sync(0xffffffffu, inc, off);
        if (lane >= off) inc += t;
    }
    if (lane == 31) wsum[w] = inc;
    __syncthreads();
    if (tid == 0) {
        int r = 0;
#pragma unroll
        for (int k = 0; k < 8; k++) { wbase[k] = r; r += wsum[k]; }
        g_cnt[b] = r;
        g_cntpad[b] = (r + 127) & ~127;
    }
    __syncthreads();
    int run = wbase[w] + inc - tot;
#pragma unroll
    for (int i = 0; i < 8; i++) {
        if (m[i]) {
            g_idx[b * SS + run] = s0 + i;
            g_jof[b * SS + s0 + i] = run;
            run++;
        }
    }
}

// ---------------------------------------------------------------------------
// K0b: gather unmasked E rows -> fp16 compact. Grid (S/8, B).
// ---------------------------------------------------------------------------
__global__ __launch_bounds__(256) void gather_convert(
    const float* __restrict__ E) {
    const int b = blockIdx.y;
    const int j0 = blockIdx.x * 8;
    const int cnt = g_cnt[b], cpad = g_cntpad[b];
    if (j0 >= cpad) return;
    const int r = threadIdx.x >> 5, lane = threadIdx.x & 31;
    const int j = j0 + r;
    const size_t dstoff = ((size_t)b * SS + j) * DD;
    if (j < cnt) {
        const int s = g_idx[b * SS + j];
        const float4* src = (const float4*)(E + ((size_t)b * SS + s) * DD);
#pragma unroll
        for (int i = 0; i < 8; i++) {
            const int c = lane + i * 32;
            *(uint2*)(g_Ech + dstoff + c * 4) = pack_h4(src[c]);
        }
    } else {
        uint2 z = {0u, 0u};
#pragma unroll
        for (int i = 0; i < 8; i++)
            *(uint2*)(g_Ech + dstoff + (lane + i * 32) * 4) = z;
    }
}

// K0c: W -> fp16. Grid 512 x 256.
__global__ __launch_bounds__(256) void wconv(const float* __restrict__ W) {
    const int t = blockIdx.x * 256 + threadIdx.x;
    const size_t off = (size_t)t * 8;
#pragma unroll
    for (int i = 0; i < 2; i++)
        *(uint2*)(g_Wh + off + i * 4) = pack_h4(*(const float4*)(W + off + i * 4));
}

// ---------------------------------------------------------------------------
// K1: dec_proj, warp-per-output. Grid 8192 x 256 (8 warps/block).
// ---------------------------------------------------------------------------
__global__ __launch_bounds__(256) void dec_proj_warp(
    const float* __restrict__ dh, const float* __restrict__ Wdec) {
    const int o = blockIdx.x * 8 + (threadIdx.x >> 5);
    const int lane = threadIdx.x & 31;
    const int b = o >> 10, d = o & 1023;
    const float4* a = (const float4*)(dh + (size_t)b * DD);
    const float4* w = (const float4*)(Wdec + (size_t)d * DD);
    float s = 0.f;
#pragma unroll
    for (int i = 0; i < 8; i++) {
        float4 av = a[lane + i * 32];
        float4 wv = w[lane + i * 32];
        s += av.x * wv.x + av.y * wv.y + av.z * wv.z + av.w * wv.w;
    }
#pragma unroll
    for (int off = 16; off >= 1; off >>= 1)
        s += __shfl_xor_sync(0xffffffffu, s, off);
    if (lane == 0) g_dec_proj[o] = s;
}

// ---------------------------------------------------------------------------
// K2 v7: fp16 m16n8k16 mma.sync GEMM on compacted rows.
// CTA 128 s x 128 d per pass, 8 passes, k-chunks of 64 (4 k16 steps),
// 3-stage cp.async pipeline. Grid (S/128, B). 8 warps = 4 (m) x 2 (n).
// smem row = 64 halfs + pad 8 = 72 halfs = 144 B.
// ---------------------------------------------------------------------------
#define RSB 144
#define TILEB (128 * RSB)       // 18432 per operand
#define BUFB (2 * TILEB)        // 36864 per stage (A + B)
#define NSTAGE 3
#define SCPO (NSTAGE * BUFB)
#define SMEM_V7 (NSTAGE * BUFB + 1024)

__global__ __launch_bounds__(256, 2) void scores_v7(
    const float* __restrict__ v) {
    extern __shared__ char sm[];
    const unsigned sbase = smem_u32(sm);
    float* scp = (float*)(sm + SCPO);

    const int tid = threadIdx.x;
    const int lane = tid & 31, wid = tid >> 5;
    const int wm = wid & 3, wn = wid >> 2;
    const int g = lane >> 2, t4 = lane & 3;
    const int b = blockIdx.y;
    const int s0 = blockIdx.x * 128;

    const int cnt = g_cnt[b];
    if (s0 >= g_cntpad[b]) return;

    scp[tid] = 0.f;

    const size_t eoff = ((size_t)b * SS + s0) * DD;
    const int crow = tid >> 1;        // 0..127
    const int ch = tid & 1;           // row half (32 halfs each)

    float acc[2][8][4];

    auto issue = [&](int it) {
        const int pass = it >> 4, kc = it & 15;
        const unsigned d0 = sbase + (unsigned)(it % NSTAGE) * BUFB;
        const int koff = kc * 64;
        const size_t es = eoff + (size_t)crow * DD + koff + ch * 32;
        const size_t ws = (size_t)(pass * 128 + crow) * DD + koff + ch * 32;
        const unsigned dst = d0 + crow * RSB + ch * 64;
#pragma unroll
        for (int i = 0; i < 4; i++) {
            cp16(dst + i * 16,         g_Ech + es + i * 8);
            cp16(dst + TILEB + i * 16, g_Wh + ws + i * 8);
        }
        CP_COMMIT();
    };

    const int lt = lane >> 3, lr = lane & 7;

    issue(0);
    issue(1);
    for (int it = 0; it < 128; it++) {
        asm volatile("cp.async.wait_group 1;" ::: "memory");
        __syncthreads();
        if (it + 2 < 128) issue(it + 2);

        if ((it & 15) == 0) {
#pragma unroll
            for (int mt = 0; mt < 2; mt++)
#pragma unroll
                for (int j = 0; j < 8; j++)
#pragma unroll
                    for (int c = 0; c < 4; c++) acc[mt][j][c] = 0.f;
        }

        const unsigned abase = sbase + (unsigned)(it % NSTAGE) * BUFB;
        const unsigned bbase = abase + TILEB;

#pragma unroll
        for (int kk = 0; kk < 4; kk++) {
            unsigned ah[2][4];
#pragma unroll
            for (int mt = 0; mt < 2; mt++) {
                const int row = 32 * wm + 16 * mt + (lt & 1) * 8 + lr;
                ldsm4(ah[mt], abase + row * RSB + kk * 32 + (lt >> 1) * 16);
            }
#pragma unroll
            for (int j2 = 0; j2 < 4; j2++) {
                const int nrow = 64 * wn + 8 * (2 * j2 + (lt >> 1)) + lr;
                unsigned bb[4];
                ldsm4(bb, bbase + nrow * RSB + kk * 32 + (lt & 1) * 16);
#pragma unroll
                for (int jj = 0; jj < 2; jj++) {
                    const int j = 2 * j2 + jj;
#pragma unroll
                    for (int mt = 0; mt < 2; mt++)
                        mma_f16(acc[mt][j], ah[mt], bb[2 * jj], bb[2 * jj + 1]);
                }
            }
        }

        if ((it & 15) == 15) {
            const int pass = it >> 4;
            const float* dpb = g_dec_proj + (size_t)b * DD + pass * 128 + wn * 64;
            const float* vb = v + pass * 128 + wn * 64;
            float p[2][2] = {{0.f, 0.f}, {0.f, 0.f}};
#pragma unroll
            for (int mt = 0; mt < 2; mt++) {
#pragma unroll
                for (int j = 0; j < 8; j++) {
                    const int c0 = 8 * j + 2 * t4;
                    const float dp0 = dpb[c0], dp1 = dpb[c0 + 1];
                    const float v0 = vb[c0], v1 = vb[c0 + 1];
                    p[mt][0] += v0 * tanha(acc[mt][j][0] + dp0) +
                                v1 * tanha(acc[mt][j][1] + dp1);
                    p[mt][1] += v0 * tanha(acc[mt][j][2] + dp0) +
                                v1 * tanha(acc[mt][j][3] + dp1);
                }
            }
#pragma unroll
            for (int off = 1; off <= 2; off <<= 1)
#pragma unroll
                for (int mt = 0; mt < 2; mt++)
#pragma unroll
                    for (int rp = 0; rp < 2; rp++)
                        p[mt][rp] += __shfl_xor_sync(0xffffffffu, p[mt][rp], off);
            if (t4 == 0) {
#pragma unroll
                for (int mt = 0; mt < 2; mt++)
#pragma unroll
                    for (int rp = 0; rp < 2; rp++)
                        scp[wn * 128 + 32 * wm + 16 * mt + g + 8 * rp] +=
                            p[mt][rp];
            }
        }
    }

    __syncthreads();
    if (tid < 128) {
        const int j = s0 + tid;
        if (j < cnt) {
            const int s = g_idx[b * SS + j];
            g_scores[b * SS + s] = scp[tid] + scp[128 + tid];
        }
    }
}

// ---------------------------------------------------------------------------
// K3: masked softmax; full attn to d_out, compact attn to g_attn_c
// ---------------------------------------------------------------------------
__global__ __launch_bounds__(256) void softmax_kernel(
    const int* __restrict__ mask, float* __restrict__ out) {
    __shared__ float red[256];
    const int b = blockIdx.x;
    const int tid = threadIdx.x;
    float vals[8];
    int msk[8];
    float mx = -INFINITY;
#pragma unroll
    for (int i = 0; i < 8; i++) {
        int s = tid + i * 256;
        size_t idx = (size_t)b * SS + s;
        msk[i] = (mask[idx] != 0);
        float scv = msk[i] ? g_scores[idx] : NEGV;
        vals[i] = scv;
        mx = fmaxf(mx, scv);
    }
    red[tid] = mx;
    __syncthreads();
    for (int off = 128; off >= 1; off >>= 1) {
        if (tid < off) red[tid] = fmaxf(red[tid], red[tid + off]);
        __syncthreads();
    }
    mx = red[0];
    __syncthreads();
    float sum = 0.f;
#pragma unroll
    for (int i = 0; i < 8; i++) {
        vals[i] = __expf(vals[i] - mx);
        sum += vals[i];
    }
    red[tid] = sum;
    __syncthreads();
    for (int off = 128; off >= 1; off >>= 1) {
        if (tid < off) red[tid] += red[tid + off];
        __syncthreads();
    }
    float inv = 1.f / red[0];
#pragma unroll
    for (int i = 0; i < 8; i++) {
        int s = tid + i * 256;
        size_t idx = (size_t)b * SS + s;
        float a = vals[i] * inv;
        out[(size_t)BB * DD + idx] = a;
        if (msk[i]) g_attn_c[(size_t)b * SS + g_jof[idx]] = a;
    }
}

// ---------------------------------------------------------------------------
// K4: context over compacted rows, reading ORIGINAL f32 E via g_idx
// (keeps context at full precision). Grid (4,4,B).
// ---------------------------------------------------------------------------
__global__ __launch_bounds__(256) void context_part(
    const float* __restrict__ E) {
    __shared__ float a_s[512];
    __shared__ int i_s[512];
    const int b = blockIdx.z, sy = blockIdx.y;
    const int e = blockIdx.x * 256 + threadIdx.x;
    const int cnt = g_cnt[b];
    for (int i = threadIdx.x; i < 512; i += 256) {
        int j = sy * 512 + i;
        bool ok = (j < cnt);
        a_s[i] = ok ? g_attn_c[(size_t)b * SS + j] : 0.f;
        i_s[i] = ok ? g_idx[b * SS + j] : 0;
    }
    __syncthreads();
    const float* Eb = E + (size_t)b * SS * DD + e;
    float c[4];
#pragma unroll
    for (int i = 0; i < 4; i++) c[i] = 0.f;
    for (int t = 0; t < 512; t += 4) {
#pragma unroll
        for (int i = 0; i < 4; i++)
            c[i] += a_s[t + i] * Eb[(size_t)i_s[t + i] * DD];
    }
    g_ctx_part[sy][(size_t)b * DD + e] = (c[0] + c[1]) + (c[2] + c[3]);
}

__global__ __launch_bounds__(256) void ctx_reduce(float* __restrict__ out) {
    const int i = blockIdx.x * 256 + threadIdx.x;
    out[i] = (g_ctx_part[0][i] + g_ctx_part[1][i]) +
             (g_ctx_part[2][i] + g_ctx_part[3][i]);
}

// ---------------------------------------------------------------------------
extern "C" void kernel_launch(void* const* d_in, const int* in_sizes, int n_in,
                              void* d_out, int out_size) {
    const float* dh   = (const float*)d_in[0];  // [64,1024]
    const float* E    = (const float*)d_in[1];  // [64,2048,1024]
    const int*   mask = (const int*)d_in[2];    // [64,2048]
    const float* Wenc = (const float*)d_in[3];  // [1024,1024]
    const float* Wdec = (const float*)d_in[4];  // [1024,1024]
    const float* v    = (const float*)d_in[5];  // [1024]
    float* out = (float*)d_out;                 // context [64,1024] ++ attn [64,2048]

    (void)cudaFuncSetAttribute(scores_v7,
                               cudaFuncAttributeMaxDynamicSharedMemorySize,
                               SMEM_V7);

    mask_scan<<<BB, 256>>>(mask);
    dim3 gg(SS / 8, BB);
    gather_convert<<<gg, 256>>>(E);
    wconv<<<512, 256>>>(Wenc);
    dec_proj_warp<<<BB * DD / 8, 256>>>(dh, Wdec);
    dim3 g2(SS / 128, BB);
    scores_v7<<<g2, 256, SMEM_V7>>>(v);
    softmax_kernel<<<BB, 256>>>(mask, out);
    dim3 g4(4, 4, BB);
    context_part<<<g4, 256>>>(E);
    ctx_reduce<<<BB * DD / 256, 256>>>(out);
}